// round 17
// baseline (speedup 1.0000x reference)
#include <cuda_runtime.h>
#include <cuda_fp16.h>
#include <cstdint>

#define T_TOKENS 8192
#define DIM      1024
#define HID      4096
#define H2       8192
#define NE       8
#define PAIRS    16384
#define TM       128
#define KC       64              // K halves per chunk (128B row)
#define ROWB     144             // padded row stride (conflict-free ldmatrix)
#define MAXTILES 136
#define NK1      (DIM/KC)        // 16
#define NK2      (HID/KC)        // 64
#define NSTG     3               // pipeline stages
#define PGRID    304             // persistent grid: 2 CTAs x 152 SMs
#define NT1      (MAXTILES * (HID / 64))   // 8704 gemm1 tiles
#define NT2      (MAXTILES * (DIM / 128))  // 1088 gemm2 tiles

// dynamic smem layout (per CTA) — 3-stage, 2 CTA/SM
#define OFF_Q    0
#define OFF_SP   16
#define OFF_BIAS 640
#define OFF_A    2048
#define ABUF     (128*ROWB)      // 18432 per stage
#define OFF_B    (OFF_A + NSTG*ABUF)
#define SMEM_TOTAL (OFF_B + NSTG*ABUF)   // 112640

// ---------------- device scratch ----------------
__device__ float  g_gate[PAIRS];
__device__ int    g_pairlist[NE * PAIRS];
__device__ int    g_count[NE];
__device__ int    g_q1, g_q2;
__device__ __half g_xb[T_TOKENS * DIM];
__device__ __half g_w1b[(size_t)NE * H2 * DIM];
__device__ __half g_w2b[(size_t)NE * DIM * HID];
__device__ __half g_hbuf[(size_t)PAIRS * HID];

// ---------------- helpers ----------------
__device__ __forceinline__ uint32_t smem_u32(const void* p) {
    return (uint32_t)__cvta_generic_to_shared(p);
}
__device__ __forceinline__ void cp16(uint32_t dst, const void* src, int sz) {
    asm volatile("cp.async.cg.shared.global [%0], [%1], 16, %2;\n" :: "r"(dst), "l"(src), "r"(sz));
}
#define CP_COMMIT() asm volatile("cp.async.commit_group;\n")
#define CP_WAIT1()  asm volatile("cp.async.wait_group 1;\n")
#define CP_WAIT0()  asm volatile("cp.async.wait_group 0;\n")

#define LDSM4(r, addr) \
    asm volatile("ldmatrix.sync.aligned.m8n8.x4.shared.b16 {%0,%1,%2,%3}, [%4];" \
        : "=r"((r)[0]), "=r"((r)[1]), "=r"((r)[2]), "=r"((r)[3]) : "r"(addr))

__device__ __forceinline__ void mma_f16(float c[4], const uint32_t a[4],
                                        uint32_t b0, uint32_t b1) {
    asm volatile(
        "mma.sync.aligned.m16n8k16.row.col.f32.f16.f16.f32 "
        "{%0,%1,%2,%3}, {%4,%5,%6,%7}, {%8,%9}, {%0,%1,%2,%3};\n"
        : "+f"(c[0]), "+f"(c[1]), "+f"(c[2]), "+f"(c[3])
        : "r"(a[0]), "r"(a[1]), "r"(a[2]), "r"(a[3]), "r"(b0), "r"(b1));
}

// map m-tile index -> (expert, m0); returns expert or -1
__device__ __forceinline__ int tile_map(int bx, int& m0, int& cnt) {
    int off = 0, e = -1;
#pragma unroll
    for (int i = 0; i < NE; i++) {
        int c = g_count[i];
        int t = (c + TM - 1) / TM;
        if (e < 0 && bx < off + t) { e = i; m0 = (bx - off) * TM; cnt = c; }
        off += t;
    }
    return e;
}

// ---------------- converts / zero / router ----------------
__device__ __forceinline__ void f2h_body(const float4* __restrict__ src,
                                         float2* __restrict__ dst, int n4) {
    int stride = gridDim.x * blockDim.x;
    for (int i = blockIdx.x * blockDim.x + threadIdx.x; i < n4; i += stride) {
        float4 v = src[i];
        union { __half2 h2[2]; float2 f; } u;
        u.h2[0] = __float22half2_rn(make_float2(v.x, v.y));
        u.h2[1] = __float22half2_rn(make_float2(v.z, v.w));
        dst[i] = u.f;
    }
}
__global__ void cvt_xw1_kernel(const float* __restrict__ x,
                               const float* __restrict__ w1) {
    f2h_body((const float4*)x,  (float2*)g_xb,  T_TOKENS * DIM / 4);
    f2h_body((const float4*)w1, (float2*)g_w1b, (int)((size_t)NE * H2 * DIM / 4));
}
__global__ void cvt_w2_kernel(const float* __restrict__ w2) {
    f2h_body((const float4*)w2, (float2*)g_w2b, (int)((size_t)NE * DIM * HID / 4));
}
__global__ void zero_out_kernel(float* __restrict__ out, int n4) {
    float4 z = make_float4(0.f, 0.f, 0.f, 0.f);
    float4* o4 = (float4*)out;
    int stride = gridDim.x * blockDim.x;
    for (int i = blockIdx.x * blockDim.x + threadIdx.x; i < n4; i += stride) o4[i] = z;
}
__global__ void zcnt_kernel() {
    if (threadIdx.x < NE) g_count[threadIdx.x] = 0;
    if (threadIdx.x == NE)     g_q1 = 0;
    if (threadIdx.x == NE + 1) g_q2 = 0;
}

__global__ void router_kernel(const float* __restrict__ x,
                              const float* __restrict__ rw,
                              const float* __restrict__ rb) {
    __shared__ float srw[NE * DIM];
    int tid = threadIdx.x;
    for (int i = tid; i < NE * DIM; i += 256) srw[i] = rw[i];
    __syncthreads();
    int warp = tid >> 5, lane = tid & 31;
    int t = blockIdx.x * 8 + warp;
    float xr[32];
#pragma unroll
    for (int i = 0; i < 32; i++) xr[i] = x[(size_t)t * DIM + i * 32 + lane];
    float lg[NE];
#pragma unroll
    for (int e = 0; e < NE; e++) {
        float s = 0.f;
#pragma unroll
        for (int i = 0; i < 32; i++) s += xr[i] * srw[e * DIM + i * 32 + lane];
#pragma unroll
        for (int o = 16; o > 0; o >>= 1) s += __shfl_xor_sync(0xffffffffu, s, o);
        lg[e] = s + rb[e];
    }
    if (lane == 0) {
        int i0 = 0;
#pragma unroll
        for (int e = 1; e < NE; e++) if (lg[e] > lg[i0]) i0 = e;
        int i1 = (i0 == 0) ? 1 : 0;
#pragma unroll
        for (int e = 0; e < NE; e++) {
            if (e == i0) continue;
            if (lg[e] > lg[i1]) i1 = e;
        }
        float e1 = __expf(lg[i1] - lg[i0]);
        g_gate[2 * t]     = 1.f / (1.f + e1);
        g_gate[2 * t + 1] = e1 / (1.f + e1);
        int pos0 = atomicAdd(&g_count[i0], 1);
        g_pairlist[i0 * PAIRS + pos0] = 2 * t;
        int pos1 = atomicAdd(&g_count[i1], 1);
        g_pairlist[i1 * PAIRS + pos1] = 2 * t + 1;
    }
}

// R16-proven mainloop: 3 stages, fills software-pipelined into ks blocks,
// fill horizon kt+2 (a part gets a full chunk of slack before its wait).
#define GEMM_MAINLOOP(NKC)                                                          \
    FILLPART(0, 0, 0); FILLPART(0, 0, 1); FILLPART(0, 0, 2); FILLPART(0, 0, 3);     \
    CP_COMMIT();                                                                    \
    FILLPART(1, 1, 0); FILLPART(1, 1, 1); FILLPART(1, 1, 2); FILLPART(1, 1, 3);     \
    CP_COMMIT();                                                                    \
    for (int kt = 0; kt < (NKC); kt++) {                                            \
        int buf = kt % NSTG;                                                        \
        if (kt + 1 < (NKC)) CP_WAIT1(); else CP_WAIT0();                            \
        __syncthreads();                                                            \
        bool pref = (kt + 2 < (NKC));                                               \
        int nb = (kt + 2) % NSTG;                                                   \
        uint32_t ab = aBase + buf * ABUF, bb = bBase + buf * ABUF;                  \
        _Pragma("unroll")                                                           \
        for (int ks = 0; ks < 4; ks++) {                                            \
            if (pref) FILLPART(nb, kt + 2, ks);                                     \
            uint32_t a[2][4], b[4][4];                                              \
            LDSM4(a[0], ab + ks * 32);                                              \
            LDSM4(a[1], ab + 16 * ROWB + ks * 32);                                  \
            _Pragma("unroll")                                                       \
            for (int j = 0; j < 4; j++) LDSM4(b[j], bb + j * 16 * ROWB + ks * 32);  \
            _Pragma("unroll")                                                       \
            for (int f = 0; f < 8; f++) {                                           \
                int j = f >> 1, h = f & 1;                                          \
                mma_f16(acc[0][f], a[0], b[j][h], b[j][h + 2]);                     \
                mma_f16(acc[1][f], a[1], b[j][h], b[j][h + 2]);                     \
            }                                                                       \
        }                                                                           \
        if (pref) CP_COMMIT();                                                      \
    }

// ---------------- GEMM1 (persistent): h = swiglu(x @ w1^T + b1) ----------------
__global__ void __launch_bounds__(256, 2) gemm1_kernel(const float* __restrict__ b1) {
    extern __shared__ __align__(1024) char sm[];
    uint32_t sb = smem_u32(sm);
    int tid = threadIdx.x;
    int*   qsl   = (int*)(sm + OFF_Q);
    int*   sp    = (int*)(sm + OFF_SP);
    float* sbias = (float*)(sm + OFF_BIAS);

    int warp = tid >> 5, lane = tid & 31;
    int wm = warp >> 1, wn = warp & 1;
    uint32_t lrow = lane & 15, lko = (lane >> 4) * 16;
    uint32_t aBase = sb + OFF_A + (wm * 32 + lrow) * ROWB + lko;
    uint32_t bBase = sb + OFF_B + (wn * 64 + lrow) * ROWB + lko;
    int kk = tid & 7, fr = tid >> 3;
    int g = lane >> 2, tg = lane & 3;

    for (;;) {
        if (tid == 0) *qsl = atomicAdd(&g_q1, 1);
        __syncthreads();          // broadcasts qsl; orders prior epilogue's sp reads before overwrite
        int qs = *qsl;
        if (qs >= NT1) break;
        int mtile = qs % MAXTILES, nt = qs / MAXTILES;
        int m0 = 0, cnt = 0;
        int e = tile_map(mtile, m0, cnt);
        if (e < 0) continue;
        int rows = min(TM, cnt - m0);
        int n0   = nt * 64;

        if (tid < TM) sp[tid] = (tid < rows) ? g_pairlist[e * PAIRS + m0 + tid] : -1;
        if (tid < 64) {
            sbias[tid]      = b1[(size_t)e * H2 + n0 + tid];
            sbias[64 + tid] = b1[(size_t)e * H2 + HID + n0 + tid];
        }
        __syncthreads();

        const __half* asrc[4]; int asz[4];
#pragma unroll
        for (int i = 0; i < 4; i++) {
            int p = sp[fr + 32 * i];
            asrc[i] = g_xb + (size_t)((p >= 0) ? (p >> 1) : 0) * DIM + kk * 8;
            asz[i]  = (p >= 0) ? 16 : 0;
        }
        const __half* wb = g_w1b + (size_t)e * H2 * DIM;
        const __half* bsrc[4];
#pragma unroll
        for (int i = 0; i < 4; i++) {
            int grow = n0 + (i >> 1) * 32 + fr + (i & 1) * HID;
            bsrc[i] = wb + (size_t)grow * DIM + kk * 8;
        }
        uint32_t adst = sb + OFF_A + fr * ROWB + kk * 16;
        uint32_t bdst = sb + OFF_B + fr * ROWB + kk * 16;

#define FILLPART(bufi, ktv, p) do {                                            \
    uint32_t ao = (bufi) * (uint32_t)ABUF; int ks_ = (ktv) * KC;               \
    cp16(adst + ao + (p) * 32 * ROWB, asrc[p] + ks_, asz[p]);                  \
    cp16(bdst + ao + (p) * 32 * ROWB, bsrc[p] + ks_, 16);                      \
    } while (0)

        float acc[2][8][4];
#pragma unroll
        for (int mi = 0; mi < 2; mi++)
#pragma unroll
            for (int f = 0; f < 8; f++)
#pragma unroll
                for (int q = 0; q < 4; q++) acc[mi][f][q] = 0.f;

        GEMM_MAINLOOP(NK1)
#undef FILLPART

#pragma unroll
        for (int mi = 0; mi < 2; mi++) {
            int rb = wm * 32 + mi * 16 + g;
#pragma unroll
            for (int f = 0; f < 4; f++) {
                int jj = wn * 32 + f * 8 + 2 * tg;
                float bg0 = sbias[jj],      bg1 = sbias[jj + 1];
                float bu0 = sbias[64 + jj], bu1 = sbias[64 + jj + 1];
                int j = n0 + jj;
                if (rb < rows) {
                    int p = sp[rb];
                    float ga = acc[mi][f][0] + bg0, ua = acc[mi][f + 4][0] + bu0;
                    float gb = acc[mi][f][1] + bg1, ub = acc[mi][f + 4][1] + bu1;
                    float h0 = ga / (1.f + __expf(-ga)) * ua;
                    float h1 = gb / (1.f + __expf(-gb)) * ub;
                    *(__half2*)&g_hbuf[(size_t)p * HID + j] = __floats2half2_rn(h0, h1);
                }
                if (rb + 8 < rows) {
                    int p = sp[rb + 8];
                    float ga = acc[mi][f][2] + bg0, ua = acc[mi][f + 4][2] + bu0;
                    float gb = acc[mi][f][3] + bg1, ub = acc[mi][f + 4][3] + bu1;
                    float h0 = ga / (1.f + __expf(-ga)) * ua;
                    float h1 = gb / (1.f + __expf(-gb)) * ub;
                    *(__half2*)&g_hbuf[(size_t)p * HID + j] = __floats2half2_rn(h0, h1);
                }
            }
        }
    }
}

// ---------------- GEMM2 (persistent): out += gate * (h @ w2^T + b2) ----------------
__global__ void __launch_bounds__(256, 2) gemm2_kernel(const float* __restrict__ b2,
                                                       float* __restrict__ out) {
    extern __shared__ __align__(1024) char sm[];
    uint32_t sb = smem_u32(sm);
    int tid = threadIdx.x;
    int*   qsl   = (int*)(sm + OFF_Q);
    int*   sp    = (int*)(sm + OFF_SP);
    float* sbias = (float*)(sm + OFF_BIAS);

    int warp = tid >> 5, lane = tid & 31;
    int wm = warp >> 1, wn = warp & 1;
    uint32_t lrow = lane & 15, lko = (lane >> 4) * 16;
    uint32_t aBase = sb + OFF_A + (wm * 32 + lrow) * ROWB + lko;
    uint32_t bBase = sb + OFF_B + (wn * 64 + lrow) * ROWB + lko;
    int kk = tid & 7, fr = tid >> 3;
    int g = lane >> 2, tg = lane & 3;

    for (;;) {
        if (tid == 0) *qsl = atomicAdd(&g_q2, 1);
        __syncthreads();
        int qs = *qsl;
        if (qs >= NT2) break;
        int mtile = qs % MAXTILES, nt = qs / MAXTILES;
        int m0 = 0, cnt = 0;
        int e = tile_map(mtile, m0, cnt);
        if (e < 0) continue;
        int rows = min(TM, cnt - m0);
        int n0   = nt * 128;

        if (tid < TM) sp[tid] = (tid < rows) ? g_pairlist[e * PAIRS + m0 + tid] : -1;
        if (tid < 128) sbias[tid] = b2[(size_t)e * DIM + n0 + tid];
        __syncthreads();

        const __half* asrc[4]; int asz[4];
#pragma unroll
        for (int i = 0; i < 4; i++) {
            int p = sp[fr + 32 * i];
            asrc[i] = g_hbuf + (size_t)((p >= 0) ? p : 0) * HID + kk * 8;
            asz[i]  = (p >= 0) ? 16 : 0;
        }
        const __half* wb = g_w2b + (size_t)e * DIM * HID;
        const __half* bsrc[4];
#pragma unroll
        for (int i = 0; i < 4; i++) bsrc[i] = wb + (size_t)(n0 + fr + 32 * i) * HID + kk * 8;
        uint32_t adst = sb + OFF_A + fr * ROWB + kk * 16;
        uint32_t bdst = sb + OFF_B + fr * ROWB + kk * 16;

#define FILLPART(bufi, ktv, p) do {                                            \
    uint32_t ao = (bufi) * (uint32_t)ABUF; int ks_ = (ktv) * KC;               \
    cp16(adst + ao + (p) * 32 * ROWB, asrc[p] + ks_, asz[p]);                  \
    cp16(bdst + ao + (p) * 32 * ROWB, bsrc[p] + ks_, 16);                      \
    } while (0)

        float acc[2][8][4];
#pragma unroll
        for (int mi = 0; mi < 2; mi++)
#pragma unroll
            for (int f = 0; f < 8; f++)
#pragma unroll
                for (int q = 0; q < 4; q++) acc[mi][f][q] = 0.f;

        GEMM_MAINLOOP(NK2)
#undef FILLPART

#pragma unroll
        for (int mi = 0; mi < 2; mi++) {
            int rb = wm * 32 + mi * 16 + g;
#pragma unroll
            for (int f = 0; f < 8; f++) {
                int jj = wn * 64 + f * 8 + 2 * tg;
                int j = n0 + jj;
                float bb0 = sbias[jj], bb1 = sbias[jj + 1];
                if (rb < rows) {
                    int p = sp[rb];
                    int t = p >> 1;
                    float w = g_gate[p];
                    atomicAdd(&out[(size_t)t * DIM + j],     (acc[mi][f][0] + bb0) * w);
                    atomicAdd(&out[(size_t)t * DIM + j + 1], (acc[mi][f][1] + bb1) * w);
                }
                if (rb + 8 < rows) {
                    int p = sp[rb + 8];
                    int t = p >> 1;
                    float w = g_gate[p];
                    atomicAdd(&out[(size_t)t * DIM + j],     (acc[mi][f][2] + bb0) * w);
                    atomicAdd(&out[(size_t)t * DIM + j + 1], (acc[mi][f][3] + bb1) * w);
                }
            }
        }
    }
}

// ---------------- launch: forked-stream schedule (R14-proven) ----------------
static cudaStream_t s1, s2, s3;
static cudaEvent_t  evR, ev1, ev2, ev3;
static bool s_init = false;

extern "C" void kernel_launch(void* const* d_in, const int* in_sizes, int n_in,
                              void* d_out, int out_size) {
    const float* x  = (const float*)d_in[0];
    const float* rw = (const float*)d_in[1];
    const float* rb = (const float*)d_in[2];
    const float* w1 = (const float*)d_in[3];
    const float* b1 = (const float*)d_in[4];
    const float* w2 = (const float*)d_in[5];
    const float* b2 = (const float*)d_in[6];
    float* out = (float*)d_out;

    if (!s_init) {
        cudaStreamCreateWithFlags(&s1, cudaStreamNonBlocking);
        cudaStreamCreateWithFlags(&s2, cudaStreamNonBlocking);
        cudaStreamCreateWithFlags(&s3, cudaStreamNonBlocking);
        cudaEventCreateWithFlags(&evR, cudaEventDisableTiming);
        cudaEventCreateWithFlags(&ev1, cudaEventDisableTiming);
        cudaEventCreateWithFlags(&ev2, cudaEventDisableTiming);
        cudaEventCreateWithFlags(&ev3, cudaEventDisableTiming);
        cudaFuncSetAttribute(gemm1_kernel, cudaFuncAttributeMaxDynamicSharedMemorySize, SMEM_TOTAL);
        cudaFuncSetAttribute(gemm2_kernel, cudaFuncAttributeMaxDynamicSharedMemorySize, SMEM_TOTAL);
        s_init = true;
    }

    cudaEventRecord(evR, 0);
    cudaStreamWaitEvent(s1, evR, 0);
    cudaStreamWaitEvent(s2, evR, 0);
    cudaStreamWaitEvent(s3, evR, 0);

    cvt_xw1_kernel<<<2048, 256, 0, s1>>>(x, w1);
    cudaEventRecord(ev1, s1);

    zcnt_kernel<<<1, 32, 0, s2>>>();
    router_kernel<<<T_TOKENS / 8, 256, 0, s2>>>(x, rw, rb);
    cudaEventRecord(ev2, s2);

    cvt_w2_kernel<<<2048, 256, 0, s3>>>(w2);
    zero_out_kernel<<<1024, 256, 0, s3>>>(out, out_size / 4);
    cudaEventRecord(ev3, s3);

    cudaStreamWaitEvent(0, ev1, 0);
    cudaStreamWaitEvent(0, ev2, 0);
    gemm1_kernel<<<PGRID, 256, SMEM_TOTAL>>>(b1);

    cudaStreamWaitEvent(0, ev3, 0);
    gemm2_kernel<<<PGRID, 256, SMEM_TOTAL>>>(b2, out);
}